// round 1
// baseline (speedup 1.0000x reference)
#include <cuda_runtime.h>
#include <math.h>

#define Bb   512
#define Cc   2048
#define HWn  48
#define NAT  51
#define HIDn 128
#define S1   8     // K-splits for pooled @ W1^T  (K=2048 -> 256/split)
#define S3   8     // K-splits for gap @ Wl^T     (K=2048 -> 256/split)

// Scratch (static __device__ globals: allocation-free rule)
__device__ float g_pooled[Bb * Cc];          // max_hw(body*A*face), 0 for non-front rows
__device__ float g_bmean [Bb * Cc];          // mean_hw(body)
__device__ float g_hp    [S1 * Bb * HIDn];   // split-K partials of pooled @ W1^T
__device__ float g_gap   [Bb * Cc];          // bmean + front*sigmoid(...)
__device__ float g_zp    [S3 * Bb * NAT];    // split-K partials of gap @ Wl^T

// ---------------------------------------------------------------------------
// K1: one streaming pass. One warp per (b,c) pair (48 contiguous floats).
//     Computes mean_hw(body) always; max_hw(body*A*face) only if pose[b]==1
//     (skips the face read entirely for non-front rows).
// ---------------------------------------------------------------------------
__global__ void __launch_bounds__(256) k1_reduce(
    const float* __restrict__ body, const float* __restrict__ face,
    const float* __restrict__ Af,   const int*   __restrict__ pose)
{
    int gw   = (blockIdx.x * 256 + threadIdx.x) >> 5;   // global warp = pair index
    int lane = threadIdx.x & 31;
    int b = gw >> 11;            // C = 2048 = 2^11
    int c = gw & (Cc - 1);
    size_t base = (size_t)gw * HWn;

    float v0 = body[base + lane];
    float v1 = (lane < 16) ? body[base + 32 + lane] : 0.0f;
    float s  = v0 + v1;

    bool front = (pose[b] == 1);
    float mx = -3.402823466e38f;
    if (front) {                                   // warp-uniform branch
        const float* ap = Af + c * HWn;
        mx = v0 * ap[lane] * face[base + lane];
        if (lane < 16) {
            float m1 = v1 * ap[32 + lane] * face[base + 32 + lane];
            mx = fmaxf(mx, m1);
        }
    }
    #pragma unroll
    for (int off = 16; off; off >>= 1) {
        s  += __shfl_xor_sync(0xffffffffu, s, off);
        mx  = fmaxf(mx, __shfl_xor_sync(0xffffffffu, mx, off));
    }
    if (lane == 0) {
        g_bmean [gw] = s * (1.0f / 48.0f);
        g_pooled[gw] = front ? mx : 0.0f;   // finite zero so MLP on dead rows stays finite
    }
}

// ---------------------------------------------------------------------------
// Generic split-K GEMM partial: Cp[s] = A[M,K-chunk] @ B[N,K-chunk]^T
// 64x64 tile, 16x16 threads, 4x4 per thread, smem stored K-major for
// float4 compute loads. N guarded (N=51 case).
// ---------------------------------------------------------------------------
__global__ void __launch_bounds__(256) gemm_splitk(
    const float* __restrict__ A, const float* __restrict__ Bm,
    float* __restrict__ Cp, int M, int N, int K, int Kc)
{
    __shared__ float As[16][68];
    __shared__ float Bs[16][68];
    int s  = blockIdx.z;
    int m0 = blockIdx.x * 64;
    int n0 = blockIdx.y * 64;
    int k0 = s * Kc;
    int tid = threadIdx.x;
    int tx = tid & 15, ty = tid >> 4;
    int r  = tid >> 2;
    int q  = (tid & 3) * 4;
    float acc[4][4] = {};

    for (int kt = 0; kt < Kc; kt += 16) {
        float4 av = *(const float4*)&A[(size_t)(m0 + r) * K + (k0 + kt + q)];
        As[q+0][r] = av.x; As[q+1][r] = av.y; As[q+2][r] = av.z; As[q+3][r] = av.w;
        float4 bv = make_float4(0.f, 0.f, 0.f, 0.f);
        if (n0 + r < N)
            bv = *(const float4*)&Bm[(size_t)(n0 + r) * K + (k0 + kt + q)];
        Bs[q+0][r] = bv.x; Bs[q+1][r] = bv.y; Bs[q+2][r] = bv.z; Bs[q+3][r] = bv.w;
        __syncthreads();
        #pragma unroll
        for (int kk = 0; kk < 16; kk++) {
            float4 a4 = *(const float4*)&As[kk][ty * 4];
            float4 b4 = *(const float4*)&Bs[kk][tx * 4];
            float a[4]  = {a4.x, a4.y, a4.z, a4.w};
            float bb[4] = {b4.x, b4.y, b4.z, b4.w};
            #pragma unroll
            for (int i = 0; i < 4; i++)
                #pragma unroll
                for (int j = 0; j < 4; j++)
                    acc[i][j] = fmaf(a[i], bb[j], acc[i][j]);
        }
        __syncthreads();
    }
    #pragma unroll
    for (int i = 0; i < 4; i++) {
        int m = m0 + ty * 4 + i;
        #pragma unroll
        for (int j = 0; j < 4; j++) {
            int n = n0 + tx * 4 + j;
            if (n < N)
                Cp[((size_t)s * M + m) * N + n] = acc[i][j];
        }
    }
}

// ---------------------------------------------------------------------------
// G2: gate/gap GEMM. A = relu(b1 + sum_s g_hp[s])  [512,128],  B = W2 [2048,128].
// Epilogue: g_gap = g_bmean + front * sigmoid(acc + b2).
// ---------------------------------------------------------------------------
__global__ void __launch_bounds__(256) gemm_gate(
    const float* __restrict__ W2,  const float* __restrict__ b1v,
    const float* __restrict__ b2v, const int*   __restrict__ pose)
{
    __shared__ float As[16][68];
    __shared__ float Bs[16][68];
    int m0 = blockIdx.x * 64;
    int n0 = blockIdx.y * 64;
    int tid = threadIdx.x;
    int tx = tid & 15, ty = tid >> 4;
    int r  = tid >> 2;
    int q  = (tid & 3) * 4;
    float acc[4][4] = {};

    for (int kt = 0; kt < HIDn; kt += 16) {
        size_t off = (size_t)(m0 + r) * HIDn + (kt + q);
        float4 av = *(const float4*)&g_hp[off];
        #pragma unroll
        for (int s2 = 1; s2 < S1; s2++) {
            const float4 t = *(const float4*)&g_hp[(size_t)s2 * (Bb * HIDn) + off];
            av.x += t.x; av.y += t.y; av.z += t.z; av.w += t.w;
        }
        const float4 bb1 = *(const float4*)&b1v[kt + q];
        av.x = fmaxf(av.x + bb1.x, 0.f);
        av.y = fmaxf(av.y + bb1.y, 0.f);
        av.z = fmaxf(av.z + bb1.z, 0.f);
        av.w = fmaxf(av.w + bb1.w, 0.f);
        As[q+0][r] = av.x; As[q+1][r] = av.y; As[q+2][r] = av.z; As[q+3][r] = av.w;
        float4 bv = *(const float4*)&W2[(size_t)(n0 + r) * HIDn + (kt + q)];
        Bs[q+0][r] = bv.x; Bs[q+1][r] = bv.y; Bs[q+2][r] = bv.z; Bs[q+3][r] = bv.w;
        __syncthreads();
        #pragma unroll
        for (int kk = 0; kk < 16; kk++) {
            float4 a4 = *(const float4*)&As[kk][ty * 4];
            float4 b4 = *(const float4*)&Bs[kk][tx * 4];
            float a[4]  = {a4.x, a4.y, a4.z, a4.w};
            float bb[4] = {b4.x, b4.y, b4.z, b4.w};
            #pragma unroll
            for (int i = 0; i < 4; i++)
                #pragma unroll
                for (int j = 0; j < 4; j++)
                    acc[i][j] = fmaf(a[i], bb[j], acc[i][j]);
        }
        __syncthreads();
    }
    #pragma unroll
    for (int i = 0; i < 4; i++) {
        int m = m0 + ty * 4 + i;
        float fr = (pose[m] == 1) ? 1.0f : 0.0f;
        #pragma unroll
        for (int j = 0; j < 4; j++) {
            int n = n0 + tx * 4 + j;
            float v = acc[i][j] + b2v[n];
            float g = 1.0f / (1.0f + expf(-v));
            g_gap[(size_t)m * Cc + n] = g_bmean[(size_t)m * Cc + n] + fr * g;
        }
    }
}

// ---------------------------------------------------------------------------
// BN: one block per attribute column. Reduces split-K z partials + bias,
// batch mean/var (biased, two-pass), normalize, write output.
// ---------------------------------------------------------------------------
__global__ void __launch_bounds__(256) bn_kernel(
    const float* __restrict__ blv, const float* __restrict__ gam,
    const float* __restrict__ bet, float* __restrict__ out)
{
    __shared__ float zbuf[Bb];
    __shared__ float red[256];
    int j   = blockIdx.x;
    int tid = threadIdx.x;
    float bias = blv[j];
    float lsum = 0.f;
    for (int b = tid; b < Bb; b += 256) {
        float z = bias;
        #pragma unroll
        for (int s = 0; s < S3; s++)
            z += g_zp[((size_t)s * Bb + b) * NAT + j];
        zbuf[b] = z;
        lsum += z;
    }
    red[tid] = lsum;
    __syncthreads();
    for (int off = 128; off; off >>= 1) {
        if (tid < off) red[tid] += red[tid + off];
        __syncthreads();
    }
    float mu = red[0] * (1.0f / Bb);
    __syncthreads();
    float lvar = 0.f;
    for (int b = tid; b < Bb; b += 256) {
        float d = zbuf[b] - mu;
        lvar += d * d;
    }
    red[tid] = lvar;
    __syncthreads();
    for (int off = 128; off; off >>= 1) {
        if (tid < off) red[tid] += red[tid + off];
        __syncthreads();
    }
    float inv = rsqrtf(red[0] * (1.0f / Bb) + 1e-5f);
    float ga = gam[j], be = bet[j];
    for (int b = tid; b < Bb; b += 256)
        out[(size_t)b * NAT + j] = ga * (zbuf[b] - mu) * inv + be;
}

// ---------------------------------------------------------------------------
extern "C" void kernel_launch(void* const* d_in, const int* in_sizes, int n_in,
                              void* d_out, int out_size)
{
    const float* body = (const float*)d_in[0];
    const float* face = (const float*)d_in[1];
    const int*   pose = (const int*)  d_in[2];   // int32 assumption (JAX x64 off)
    const float* Af   = (const float*)d_in[3];
    const float* W1   = (const float*)d_in[4];
    const float* b1v  = (const float*)d_in[5];
    const float* W2   = (const float*)d_in[6];
    const float* b2v  = (const float*)d_in[7];
    const float* Wl   = (const float*)d_in[8];
    const float* blv  = (const float*)d_in[9];
    const float* gam  = (const float*)d_in[10];
    const float* bet  = (const float*)d_in[11];
    float* out = (float*)d_out;

    float *pooled_p, *gap_p, *hp_p, *zp_p;
    cudaGetSymbolAddress((void**)&pooled_p, g_pooled);
    cudaGetSymbolAddress((void**)&gap_p,    g_gap);
    cudaGetSymbolAddress((void**)&hp_p,     g_hp);
    cudaGetSymbolAddress((void**)&zp_p,     g_zp);

    // 1) streaming reduce: pooled max + body mean
    k1_reduce<<<(Bb * Cc) / 8, 256>>>(body, face, Af, pose);
    // 2) hp[s] = pooled @ W1^T  (split-K partials)
    gemm_splitk<<<dim3(Bb / 64, HIDn / 64, S1), 256>>>(pooled_p, W1, hp_p,
                                                       Bb, HIDn, Cc, Cc / S1);
    // 3) gap = bmean + front * sigmoid(relu(sum hp + b1) @ W2^T + b2)
    gemm_gate<<<dim3(Bb / 64, Cc / 64), 256>>>(W2, b1v, b2v, pose);
    // 4) zp[s] = gap @ Wl^T  (split-K partials)
    gemm_splitk<<<dim3(Bb / 64, 1, S3), 256>>>(gap_p, Wl, zp_p,
                                               Bb, NAT, Cc, Cc / S3);
    // 5) reduce partials + bias + batchnorm
    bn_kernel<<<NAT, 256>>>(blv, gam, bet, out);
}

// round 3
// speedup vs baseline: 1.1402x; 1.1402x over previous
#include <cuda_runtime.h>
#include <math.h>
#include <float.h>

#define Bb   512
#define Cc   2048
#define HWn  48
#define NAT  51
#define HIDn 128
#define S1   16    // K-splits for pooled @ W1^T  (K=2048 -> 128/split)
#define NTIL 32    // channel tiles in gate kernel (2048/64), each emits a z-partial

// Scratch (static __device__ globals: allocation-free rule)
__device__ float g_pooled[Bb * Cc];            // max_hw(body*A*face), 0 for non-front rows
__device__ float g_bmean [Bb * Cc];            // mean_hw(body)
__device__ float g_hp    [S1 * Bb * HIDn];     // split-K partials of pooled @ W1^T
__device__ float g_h     [Bb * HIDn];          // relu(sum hp + b1)
__device__ float g_zp    [NTIL * NAT * Bb];    // per-n-tile partials of gap @ Wl^T, layout [nt][j][b]

// ---------------------------------------------------------------------------
// K1: one streaming pass. One warp per (b,c) pair. float2 loads, 24 active
// lanes. mean_hw(body) always; max_hw(body*A*face) only for front rows.
// Results staged through smem so global writes are coalesced sectors.
// ---------------------------------------------------------------------------
__global__ void __launch_bounds__(256) k1_reduce(
    const float* __restrict__ body, const float* __restrict__ face,
    const float* __restrict__ Af,   const int*   __restrict__ pose)
{
    __shared__ float sm_mean[8];
    __shared__ float sm_max [8];
    int tid  = threadIdx.x;
    int wid  = tid >> 5;
    int lane = tid & 31;
    int gw   = blockIdx.x * 8 + wid;       // global (b,c) pair index
    int b = gw >> 11;
    int c = gw & (Cc - 1);

    const float2* b2 = (const float2*)body + (size_t)gw * 24;
    bool act = (lane < 24);
    float2 bv = act ? b2[lane] : make_float2(0.f, 0.f);
    float s = bv.x + bv.y;

    bool front = (pose[b] == 1);
    float mx = -FLT_MAX;
    if (front && act) {
        const float2* f2 = (const float2*)face + (size_t)gw * 24;
        const float2* a2 = (const float2*)Af + (size_t)c * 24;
        float2 fv = f2[lane];
        float2 av = a2[lane];
        mx = fmaxf(bv.x * av.x * fv.x, bv.y * av.y * fv.y);
    }
    #pragma unroll
    for (int off = 16; off; off >>= 1) {
        s  += __shfl_xor_sync(0xffffffffu, s, off);
        mx  = fmaxf(mx, __shfl_xor_sync(0xffffffffu, mx, off));
    }
    if (lane == 0) {
        sm_mean[wid] = s * (1.0f / 48.0f);
        sm_max [wid] = front ? mx : 0.0f;
    }
    __syncthreads();
    int base = blockIdx.x * 8;
    if (tid < 8)       g_bmean [base + tid]     = sm_mean[tid];
    else if (tid < 16) g_pooled[base + tid - 8] = sm_max [tid - 8];
}

// ---------------------------------------------------------------------------
// GEMM1 split-K: hp[s] = pooled[512, k-chunk] @ W1[128, k-chunk]^T
// 64x64 tile, register-prefetch pipeline over k-tiles.
// ---------------------------------------------------------------------------
__global__ void __launch_bounds__(256) gemm1(
    const float* __restrict__ A, const float* __restrict__ Bw,
    float* __restrict__ hp)
{
    __shared__ float As[16][68];
    __shared__ float Bs[16][68];
    int s  = blockIdx.z;
    int m0 = blockIdx.x * 64;
    int n0 = blockIdx.y * 64;
    int k0 = s * (Cc / S1);                 // 128-wide chunk
    int tid = threadIdx.x;
    int tx = tid & 15, ty = tid >> 4;
    int r  = tid >> 2;
    int q  = (tid & 3) * 4;
    float acc[4][4] = {};

    const float* ap = &A [(size_t)(m0 + r) * Cc + k0 + q];
    const float* bp = &Bw[(size_t)(n0 + r) * Cc + k0 + q];
    float4 areg = *(const float4*)ap;
    float4 breg = *(const float4*)bp;

    #pragma unroll
    for (int kt = 0; kt < Cc / S1; kt += 16) {
        As[q+0][r] = areg.x; As[q+1][r] = areg.y; As[q+2][r] = areg.z; As[q+3][r] = areg.w;
        Bs[q+0][r] = breg.x; Bs[q+1][r] = breg.y; Bs[q+2][r] = breg.z; Bs[q+3][r] = breg.w;
        __syncthreads();
        if (kt + 16 < Cc / S1) {
            areg = *(const float4*)(ap + kt + 16);
            breg = *(const float4*)(bp + kt + 16);
        }
        #pragma unroll
        for (int kk = 0; kk < 16; kk++) {
            float4 a4 = *(const float4*)&As[kk][ty * 4];
            float4 b4 = *(const float4*)&Bs[kk][tx * 4];
            float a[4]  = {a4.x, a4.y, a4.z, a4.w};
            float bb[4] = {b4.x, b4.y, b4.z, b4.w};
            #pragma unroll
            for (int i = 0; i < 4; i++)
                #pragma unroll
                for (int j = 0; j < 4; j++)
                    acc[i][j] = fmaf(a[i], bb[j], acc[i][j]);
        }
        __syncthreads();
    }
    #pragma unroll
    for (int i = 0; i < 4; i++) {
        int m = m0 + ty * 4 + i;
        #pragma unroll
        for (int j = 0; j < 4; j++) {
            int n = n0 + tx * 4 + j;
            hp[((size_t)s * Bb + m) * HIDn + n] = acc[i][j];
        }
    }
}

// ---------------------------------------------------------------------------
// hreduce: h = relu(sum_s hp[s] + b1), float4 over 512*128 elems.
// ---------------------------------------------------------------------------
__global__ void __launch_bounds__(256) hreduce(const float* __restrict__ b1v)
{
    int i4 = blockIdx.x * 256 + threadIdx.x;          // 16384 float4s
    float4 v = *(const float4*)&g_hp[(size_t)i4 * 4];
    #pragma unroll
    for (int s = 1; s < S1; s++) {
        float4 t = *(const float4*)&g_hp[(size_t)s * (Bb * HIDn) + (size_t)i4 * 4];
        v.x += t.x; v.y += t.y; v.z += t.z; v.w += t.w;
    }
    float4 bv = *(const float4*)&b1v[(i4 & 31) * 4];
    v.x = fmaxf(v.x + bv.x, 0.f);
    v.y = fmaxf(v.y + bv.y, 0.f);
    v.z = fmaxf(v.z + bv.z, 0.f);
    v.w = fmaxf(v.w + bv.w, 0.f);
    *(float4*)&g_h[(size_t)i4 * 4] = v;
}

// ---------------------------------------------------------------------------
// GATE: mainloop gap_tile = bmean + front*sigmoid(h @ W2^T + b2) for a
// 64(batch)x64(channel) tile, then a fused mini-GEMM epilogue emits
// the z-partial  zp[ntile][51][512]  (deterministic per-n-tile partials).
// smem reused: mainloop As/Bs region overlaps gapT (sync-separated).
// WlT padded to 68 cols so the float4 reads at tx*4 (up to 63) stay in-bounds.
// ---------------------------------------------------------------------------
__global__ void __launch_bounds__(256) gemm_gate(
    const float* __restrict__ W2,  const float* __restrict__ b2v,
    const float* __restrict__ Wl,  const int*   __restrict__ pose)
{
    __shared__ __align__(16) float smemBuf[64 * 68 + 64 * 68];   // 34816 B
    float (*As)[68]   = (float(*)[68]) smemBuf;                  // [16][68]
    float (*Bs)[68]   = (float(*)[68])(smemBuf + 16 * 68);       // [16][68]
    float (*gapT)[68] = (float(*)[68]) smemBuf;                  // [64][68] (chan-major)
    float (*WlT)[68]  = (float(*)[68])(smemBuf + 64 * 68);       // [64][68] (padded: j=51..67 zero)

    int m0 = blockIdx.x * 64;
    int n0 = blockIdx.y * 64;
    int tid = threadIdx.x;
    int tx = tid & 15, ty = tid >> 4;
    int r  = tid >> 2;
    int q  = (tid & 3) * 4;
    float acc[4][4] = {};

    const float* ap = &g_h[(size_t)(m0 + r) * HIDn + q];
    const float* bp = &W2 [(size_t)(n0 + r) * HIDn + q];
    float4 areg = *(const float4*)ap;
    float4 breg = *(const float4*)bp;

    #pragma unroll
    for (int kt = 0; kt < HIDn; kt += 16) {
        As[q+0][r] = areg.x; As[q+1][r] = areg.y; As[q+2][r] = areg.z; As[q+3][r] = areg.w;
        Bs[q+0][r] = breg.x; Bs[q+1][r] = breg.y; Bs[q+2][r] = breg.z; Bs[q+3][r] = breg.w;
        __syncthreads();
        if (kt + 16 < HIDn) {
            areg = *(const float4*)(ap + kt + 16);
            breg = *(const float4*)(bp + kt + 16);
        }
        #pragma unroll
        for (int kk = 0; kk < 16; kk++) {
            float4 a4 = *(const float4*)&As[kk][ty * 4];
            float4 b4 = *(const float4*)&Bs[kk][tx * 4];
            float a[4]  = {a4.x, a4.y, a4.z, a4.w};
            float bb[4] = {b4.x, b4.y, b4.z, b4.w};
            #pragma unroll
            for (int i = 0; i < 4; i++)
                #pragma unroll
                for (int j = 0; j < 4; j++)
                    acc[i][j] = fmaf(a[i], bb[j], acc[i][j]);
        }
        __syncthreads();
    }

    // --- epilogue: gap values -> gapT (chan-major). As/Bs reuse is safe:
    // mainloop ends with __syncthreads(), gapT/WlT are disjoint regions.
    #pragma unroll
    for (int i = 0; i < 4; i++) {
        int m = m0 + ty * 4 + i;
        float fr = (pose[m] == 1) ? 1.0f : 0.0f;
        #pragma unroll
        for (int j = 0; j < 4; j++) {
            int n = n0 + tx * 4 + j;
            float v = acc[i][j] + b2v[n];
            float g = 1.0f / (1.0f + expf(-v));
            gapT[tx * 4 + j][ty * 4 + i] =
                g_bmean[(size_t)m * Cc + n] + fr * g;
        }
    }
    // Load Wl chunk (51 attrs x 64 channels) transposed into WlT[cc][j];
    // zero-fill the full padded width j=51..67.
    for (int idx = tid; idx < 64 * 68; idx += 256) {
        int cc = idx / 68, j = idx - cc * 68;
        WlT[cc][j] = (j < NAT) ? Wl[(size_t)j * Cc + n0 + cc] : 0.f;
    }
    __syncthreads();

    // mini-GEMM: zpart[row, attr] = sum_cc gapT[cc][row] * WlT[cc][attr]
    float acc2[4][4] = {};
    #pragma unroll 8
    for (int cc = 0; cc < 64; cc++) {
        float4 g4 = *(const float4*)&gapT[cc][ty * 4];
        float4 w4 = *(const float4*)&WlT [cc][tx * 4];
        float gg[4] = {g4.x, g4.y, g4.z, g4.w};
        float ww[4] = {w4.x, w4.y, w4.z, w4.w};
        #pragma unroll
        for (int i = 0; i < 4; i++)
            #pragma unroll
            for (int j = 0; j < 4; j++)
                acc2[i][j] = fmaf(gg[i], ww[j], acc2[i][j]);
    }
    int nt = blockIdx.y;
    #pragma unroll
    for (int j = 0; j < 4; j++) {
        int attr = tx * 4 + j;
        if (attr < NAT) {
            #pragma unroll
            for (int i = 0; i < 4; i++) {
                int m = m0 + ty * 4 + i;
                g_zp[((size_t)nt * NAT + attr) * Bb + m] = acc2[i][j];
            }
        }
    }
}

// ---------------------------------------------------------------------------
// BN: one block per attribute. Reduce 32 n-tile partials (coalesced over b),
// add bias, batch mean/var (biased), normalize, write.
// ---------------------------------------------------------------------------
__global__ void __launch_bounds__(256) bn_kernel(
    const float* __restrict__ blv, const float* __restrict__ gam,
    const float* __restrict__ bet, float* __restrict__ out)
{
    __shared__ float zbuf[Bb];
    __shared__ float red[256];
    int j   = blockIdx.x;
    int tid = threadIdx.x;
    float bias = blv[j];
    float lsum = 0.f;
    for (int b = tid; b < Bb; b += 256) {
        float z = bias;
        #pragma unroll
        for (int nt = 0; nt < NTIL; nt++)
            z += g_zp[((size_t)nt * NAT + j) * Bb + b];
        zbuf[b] = z;
        lsum += z;
    }
    red[tid] = lsum;
    __syncthreads();
    for (int off = 128; off; off >>= 1) {
        if (tid < off) red[tid] += red[tid + off];
        __syncthreads();
    }
    float mu = red[0] * (1.0f / Bb);
    __syncthreads();
    float lvar = 0.f;
    for (int b = tid; b < Bb; b += 256) {
        float d = zbuf[b] - mu;
        lvar += d * d;
    }
    red[tid] = lvar;
    __syncthreads();
    for (int off = 128; off; off >>= 1) {
        if (tid < off) red[tid] += red[tid + off];
        __syncthreads();
    }
    float inv = rsqrtf(red[0] * (1.0f / Bb) + 1e-5f);
    float ga = gam[j], be = bet[j];
    for (int b = tid; b < Bb; b += 256)
        out[(size_t)b * NAT + j] = ga * (zbuf[b] - mu) * inv + be;
}

// ---------------------------------------------------------------------------
extern "C" void kernel_launch(void* const* d_in, const int* in_sizes, int n_in,
                              void* d_out, int out_size)
{
    const float* body = (const float*)d_in[0];
    const float* face = (const float*)d_in[1];
    const int*   pose = (const int*)  d_in[2];
    const float* Af   = (const float*)d_in[3];
    const float* W1   = (const float*)d_in[4];
    const float* b1v  = (const float*)d_in[5];
    const float* W2   = (const float*)d_in[6];
    const float* b2v  = (const float*)d_in[7];
    const float* Wl   = (const float*)d_in[8];
    const float* blv  = (const float*)d_in[9];
    const float* gam  = (const float*)d_in[10];
    const float* bet  = (const float*)d_in[11];
    float* out = (float*)d_out;

    float *pooled_p, *hp_p;
    cudaGetSymbolAddress((void**)&pooled_p, g_pooled);
    cudaGetSymbolAddress((void**)&hp_p,     g_hp);

    // 1) streaming reduce: pooled max + body mean
    k1_reduce<<<(Bb * Cc) / 8, 256>>>(body, face, Af, pose);
    // 2) hp[s] = pooled @ W1^T  (16-way split-K partials)
    gemm1<<<dim3(Bb / 64, HIDn / 64, S1), 256>>>(pooled_p, W1, hp_p);
    // 3) h = relu(sum hp + b1)
    hreduce<<<(Bb * HIDn / 4) / 256, 256>>>(b1v);
    // 4) gate GEMM + fused z-partial epilogue
    gemm_gate<<<dim3(Bb / 64, NTIL), 256>>>(W2, b2v, Wl, pose);
    // 5) reduce partials + bias + batchnorm
    bn_kernel<<<NAT, 256>>>(blv, gam, bet, out);
}

// round 4
// speedup vs baseline: 1.8868x; 1.6548x over previous
#include <cuda_runtime.h>
#include <math.h>
#include <float.h>

#define Bb   512
#define Cc   2048
#define HWn  48
#define NAT  51
#define HIDn 128
#define S1   16    // K-splits for pooled @ W1^T  (K=2048 -> 128/split)
#define NTIL 32    // channel tiles in gate kernel (2048/64), each emits a z-partial

// Scratch (static __device__ globals: allocation-free rule)
__device__ float g_pooled[Bb * Cc];            // max_hw(body*A*face), 0 for non-front rows
__device__ float g_bmean [Bb * Cc];            // mean_hw(body)
__device__ float g_hp    [S1 * Bb * HIDn];     // split-K partials of pooled @ W1^T
__device__ float g_h     [Bb * HIDn];          // relu(sum hp + b1)
__device__ float g_zp    [NTIL * NAT * Bb];    // per-n-tile partials of gap @ Wl^T, layout [nt][j][b]

// ---------------------------------------------------------------------------
// K1: streaming pass. Each warp handles 8 contiguous channels = 192 float2 =
// 6 fully-active coalesced iterations (MLP 6-18). Channels are contiguous, so
// body/face/Af all use the same linear index. Reduction via smem (4 lanes per
// channel + 2 shfl levels) instead of 10 shuffles/channel. Coalesced output.
// ---------------------------------------------------------------------------
__global__ void __launch_bounds__(256) k1_reduce(
    const float* __restrict__ body, const float* __restrict__ face,
    const float* __restrict__ Af,   const int*   __restrict__ pose)
{
    __shared__ float sm_s[8][192];
    __shared__ float sm_m[8][192];
    __shared__ float out_s[64], out_m[64];
    int tid  = threadIdx.x;
    int wid  = tid >> 5;
    int lane = tid & 31;
    int blk_ch = blockIdx.x * 64;          // base (b*2048+c): block = 64 channels of ONE b
    int b = blk_ch >> 11;
    bool front = (pose[b] == 1);
    int wbase = blk_ch + wid * 8;          // this warp's first channel-pair index

    const float2* bp = (const float2*)body + (size_t)wbase * 24;
    float2 bvv[6];
    float  s[6];
    #pragma unroll
    for (int k = 0; k < 6; k++) {
        bvv[k] = bp[k * 32 + lane];
        s[k] = bvv[k].x + bvv[k].y;
    }
    if (front) {
        const float2* fp = (const float2*)face + (size_t)wbase * 24;
        const float2* ap = (const float2*)Af   + (size_t)(wbase & (Cc - 1)) * 24;
        #pragma unroll
        for (int k = 0; k < 6; k++) {
            float2 fv = fp[k * 32 + lane];
            float2 av = ap[k * 32 + lane];
            sm_m[wid][k * 32 + lane] =
                fmaxf(bvv[k].x * av.x * fv.x, bvv[k].y * av.y * fv.y);
        }
    }
    #pragma unroll
    for (int k = 0; k < 6; k++)
        sm_s[wid][k * 32 + lane] = s[k];
    __syncthreads();

    // Phase 2: 4 threads per channel; thread t -> channel t>>2, segment t&3.
    {
        int chl = tid >> 2;                // 0..63 local channel
        int w2  = chl >> 3;                // source warp
        int off = (chl & 7) * 24 + (tid & 3) * 6;
        float ss = 0.f;
        #pragma unroll
        for (int i = 0; i < 6; i++) ss += sm_s[w2][off + i];
        ss += __shfl_xor_sync(0xffffffffu, ss, 1);
        ss += __shfl_xor_sync(0xffffffffu, ss, 2);
        float mm = 0.f;
        if (front) {
            mm = -FLT_MAX;
            #pragma unroll
            for (int i = 0; i < 6; i++) mm = fmaxf(mm, sm_m[w2][off + i]);
            mm = fmaxf(mm, __shfl_xor_sync(0xffffffffu, mm, 1));
            mm = fmaxf(mm, __shfl_xor_sync(0xffffffffu, mm, 2));
        }
        if ((tid & 3) == 0) {
            out_s[chl] = ss * (1.0f / 48.0f);
            out_m[chl] = mm;
        }
    }
    __syncthreads();
    if (tid < 64)        g_bmean [blk_ch + tid]      = out_s[tid];
    else if (tid < 128)  g_pooled[blk_ch + tid - 64] = out_m[tid - 64];
}

// ---------------------------------------------------------------------------
// GEMM1 split-K: hp[s] = pooled[512, k-chunk] @ W1[128, k-chunk]^T
// ---------------------------------------------------------------------------
__global__ void __launch_bounds__(256) gemm1(
    const float* __restrict__ A, const float* __restrict__ Bw,
    float* __restrict__ hp)
{
    __shared__ float As[16][68];
    __shared__ float Bs[16][68];
    int s  = blockIdx.z;
    int m0 = blockIdx.x * 64;
    int n0 = blockIdx.y * 64;
    int k0 = s * (Cc / S1);
    int tid = threadIdx.x;
    int tx = tid & 15, ty = tid >> 4;
    int r  = tid >> 2;
    int q  = (tid & 3) * 4;
    float acc[4][4] = {};

    const float* ap = &A [(size_t)(m0 + r) * Cc + k0 + q];
    const float* bp = &Bw[(size_t)(n0 + r) * Cc + k0 + q];
    float4 areg = *(const float4*)ap;
    float4 breg = *(const float4*)bp;

    #pragma unroll
    for (int kt = 0; kt < Cc / S1; kt += 16) {
        As[q+0][r] = areg.x; As[q+1][r] = areg.y; As[q+2][r] = areg.z; As[q+3][r] = areg.w;
        Bs[q+0][r] = breg.x; Bs[q+1][r] = breg.y; Bs[q+2][r] = breg.z; Bs[q+3][r] = breg.w;
        __syncthreads();
        if (kt + 16 < Cc / S1) {
            areg = *(const float4*)(ap + kt + 16);
            breg = *(const float4*)(bp + kt + 16);
        }
        #pragma unroll
        for (int kk = 0; kk < 16; kk++) {
            float4 a4 = *(const float4*)&As[kk][ty * 4];
            float4 b4 = *(const float4*)&Bs[kk][tx * 4];
            float a[4]  = {a4.x, a4.y, a4.z, a4.w};
            float bb[4] = {b4.x, b4.y, b4.z, b4.w};
            #pragma unroll
            for (int i = 0; i < 4; i++)
                #pragma unroll
                for (int j = 0; j < 4; j++)
                    acc[i][j] = fmaf(a[i], bb[j], acc[i][j]);
        }
        __syncthreads();
    }
    #pragma unroll
    for (int i = 0; i < 4; i++) {
        int m = m0 + ty * 4 + i;
        #pragma unroll
        for (int j = 0; j < 4; j++) {
            int n = n0 + tx * 4 + j;
            hp[((size_t)s * Bb + m) * HIDn + n] = acc[i][j];
        }
    }
}

// ---------------------------------------------------------------------------
// hreduce: h = relu(sum_s hp[s] + b1)
// ---------------------------------------------------------------------------
__global__ void __launch_bounds__(256) hreduce(const float* __restrict__ b1v)
{
    int i4 = blockIdx.x * 256 + threadIdx.x;
    float4 v = *(const float4*)&g_hp[(size_t)i4 * 4];
    #pragma unroll
    for (int s = 1; s < S1; s++) {
        float4 t = *(const float4*)&g_hp[(size_t)s * (Bb * HIDn) + (size_t)i4 * 4];
        v.x += t.x; v.y += t.y; v.z += t.z; v.w += t.w;
    }
    float4 bv = *(const float4*)&b1v[(i4 & 31) * 4];
    v.x = fmaxf(v.x + bv.x, 0.f);
    v.y = fmaxf(v.y + bv.y, 0.f);
    v.z = fmaxf(v.z + bv.z, 0.f);
    v.w = fmaxf(v.w + bv.w, 0.f);
    *(float4*)&g_h[(size_t)i4 * 4] = v;
}

// ---------------------------------------------------------------------------
// GATE: 64x64 gap tile = bmean + front*sigmoid(h @ W2^T + b2), then fused
// z-partial epilogue in TWO 32-channel passes (smem union 17.4 KB -> ~4
// blocks/SM instead of 2).
// ---------------------------------------------------------------------------
__global__ void __launch_bounds__(256) gemm_gate(
    const float* __restrict__ W2,  const float* __restrict__ b2v,
    const float* __restrict__ Wl,  const int*   __restrict__ pose)
{
    __shared__ __align__(16) float smemBuf[32 * 68 + 32 * 68];   // 17408 B
    float (*As)[68]   = (float(*)[68]) smemBuf;                  // [16][68]
    float (*Bs)[68]   = (float(*)[68])(smemBuf + 16 * 68);       // [16][68]
    float (*gapT)[68] = (float(*)[68]) smemBuf;                  // [32][68]
    float (*WlT)[68]  = (float(*)[68])(smemBuf + 32 * 68);       // [32][68] (j>=51 zero)

    int m0 = blockIdx.x * 64;
    int n0 = blockIdx.y * 64;
    int tid = threadIdx.x;
    int tx = tid & 15, ty = tid >> 4;
    int r  = tid >> 2;
    int q  = (tid & 3) * 4;
    float acc[4][4] = {};

    const float* ap = &g_h[(size_t)(m0 + r) * HIDn + q];
    const float* bp = &W2 [(size_t)(n0 + r) * HIDn + q];
    float4 areg = *(const float4*)ap;
    float4 breg = *(const float4*)bp;

    #pragma unroll
    for (int kt = 0; kt < HIDn; kt += 16) {
        As[q+0][r] = areg.x; As[q+1][r] = areg.y; As[q+2][r] = areg.z; As[q+3][r] = areg.w;
        Bs[q+0][r] = breg.x; Bs[q+1][r] = breg.y; Bs[q+2][r] = breg.z; Bs[q+3][r] = breg.w;
        __syncthreads();
        if (kt + 16 < HIDn) {
            areg = *(const float4*)(ap + kt + 16);
            breg = *(const float4*)(bp + kt + 16);
        }
        #pragma unroll
        for (int kk = 0; kk < 16; kk++) {
            float4 a4 = *(const float4*)&As[kk][ty * 4];
            float4 b4 = *(const float4*)&Bs[kk][tx * 4];
            float a[4]  = {a4.x, a4.y, a4.z, a4.w};
            float bb[4] = {b4.x, b4.y, b4.z, b4.w};
            #pragma unroll
            for (int i = 0; i < 4; i++)
                #pragma unroll
                for (int j = 0; j < 4; j++)
                    acc[i][j] = fmaf(a[i], bb[j], acc[i][j]);
        }
        __syncthreads();
    }
    // mainloop ends with __syncthreads(): As/Bs region is free to reuse.

    float fr[4];
    #pragma unroll
    for (int i = 0; i < 4; i++)
        fr[i] = (pose[m0 + ty * 4 + i] == 1) ? 1.0f : 0.0f;

    float acc2[4][4] = {};
    #pragma unroll
    for (int p = 0; p < 2; p++) {
        // gap values for channels [n0+32p, n0+32p+32) -> gapT (chan-major)
        if ((tx >> 3) == p) {
            #pragma unroll
            for (int i = 0; i < 4; i++) {
                int m = m0 + ty * 4 + i;
                #pragma unroll
                for (int j = 0; j < 4; j++) {
                    int n = n0 + tx * 4 + j;
                    float v = acc[i][j] + b2v[n];
                    float g = 1.0f / (1.0f + expf(-v));
                    gapT[(tx - 8 * p) * 4 + j][ty * 4 + i] =
                        g_bmean[(size_t)m * Cc + n] + fr[i] * g;
                }
            }
        }
        // Wl chunk for these 32 channels, transposed+padded
        for (int idx = tid; idx < 32 * 68; idx += 256) {
            int cc = idx / 68, j = idx - cc * 68;
            WlT[cc][j] = (j < NAT) ? Wl[(size_t)j * Cc + n0 + 32 * p + cc] : 0.f;
        }
        __syncthreads();
        #pragma unroll 8
        for (int cc = 0; cc < 32; cc++) {
            float4 g4 = *(const float4*)&gapT[cc][ty * 4];
            float4 w4 = *(const float4*)&WlT [cc][tx * 4];
            float gg[4] = {g4.x, g4.y, g4.z, g4.w};
            float ww[4] = {w4.x, w4.y, w4.z, w4.w};
            #pragma unroll
            for (int i = 0; i < 4; i++)
                #pragma unroll
                for (int j = 0; j < 4; j++)
                    acc2[i][j] = fmaf(gg[i], ww[j], acc2[i][j]);
        }
        __syncthreads();
    }

    int nt = blockIdx.y;
    #pragma unroll
    for (int j = 0; j < 4; j++) {
        int attr = tx * 4 + j;
        if (attr < NAT) {
            #pragma unroll
            for (int i = 0; i < 4; i++) {
                int m = m0 + ty * 4 + i;
                g_zp[((size_t)nt * NAT + attr) * Bb + m] = acc2[i][j];
            }
        }
    }
}

// ---------------------------------------------------------------------------
// BN: one block per attribute.
// ---------------------------------------------------------------------------
__global__ void __launch_bounds__(256) bn_kernel(
    const float* __restrict__ blv, const float* __restrict__ gam,
    const float* __restrict__ bet, float* __restrict__ out)
{
    __shared__ float zbuf[Bb];
    __shared__ float red[256];
    int j   = blockIdx.x;
    int tid = threadIdx.x;
    float bias = blv[j];
    float lsum = 0.f;
    for (int b = tid; b < Bb; b += 256) {
        float z = bias;
        #pragma unroll
        for (int nt = 0; nt < NTIL; nt++)
            z += g_zp[((size_t)nt * NAT + j) * Bb + b];
        zbuf[b] = z;
        lsum += z;
    }
    red[tid] = lsum;
    __syncthreads();
    for (int off = 128; off; off >>= 1) {
        if (tid < off) red[tid] += red[tid + off];
        __syncthreads();
    }
    float mu = red[0] * (1.0f / Bb);
    __syncthreads();
    float lvar = 0.f;
    for (int b = tid; b < Bb; b += 256) {
        float d = zbuf[b] - mu;
        lvar += d * d;
    }
    red[tid] = lvar;
    __syncthreads();
    for (int off = 128; off; off >>= 1) {
        if (tid < off) red[tid] += red[tid + off];
        __syncthreads();
    }
    float inv = rsqrtf(red[0] * (1.0f / Bb) + 1e-5f);
    float ga = gam[j], be = bet[j];
    for (int b = tid; b < Bb; b += 256)
        out[(size_t)b * NAT + j] = ga * (zbuf[b] - mu) * inv + be;
}

// ---------------------------------------------------------------------------
extern "C" void kernel_launch(void* const* d_in, const int* in_sizes, int n_in,
                              void* d_out, int out_size)
{
    const float* body = (const float*)d_in[0];
    const float* face = (const float*)d_in[1];
    const int*   pose = (const int*)  d_in[2];
    const float* Af   = (const float*)d_in[3];
    const float* W1   = (const float*)d_in[4];
    const float* b1v  = (const float*)d_in[5];
    const float* W2   = (const float*)d_in[6];
    const float* b2v  = (const float*)d_in[7];
    const float* Wl   = (const float*)d_in[8];
    const float* blv  = (const float*)d_in[9];
    const float* gam  = (const float*)d_in[10];
    const float* bet  = (const float*)d_in[11];
    float* out = (float*)d_out;

    float *pooled_p, *hp_p;
    cudaGetSymbolAddress((void**)&pooled_p, g_pooled);
    cudaGetSymbolAddress((void**)&hp_p,     g_hp);

    // 1) streaming reduce: pooled max + body mean (64 channels/block)
    k1_reduce<<<(Bb * Cc) / 64, 256>>>(body, face, Af, pose);
    // 2) hp[s] = pooled @ W1^T  (16-way split-K partials)
    gemm1<<<dim3(Bb / 64, HIDn / 64, S1), 256>>>(pooled_p, W1, hp_p);
    // 3) h = relu(sum hp + b1)
    hreduce<<<(Bb * HIDn / 4) / 256, 256>>>(b1v);
    // 4) gate GEMM + fused z-partial epilogue (2-pass, low smem)
    gemm_gate<<<dim3(Bb / 64, NTIL), 256>>>(W2, b2v, Wl, pose);
    // 5) reduce partials + bias + batchnorm
    bn_kernel<<<NAT, 256>>>(blv, gam, bet, out);
}

// round 5
// speedup vs baseline: 1.9705x; 1.0444x over previous
#include <cuda_runtime.h>
#include <math.h>
#include <float.h>

#define Bb   512
#define Cc   2048
#define HWn  48
#define NAT  51
#define HIDn 128
#define S1   16    // K-splits for pooled @ W1^T  (K=2048 -> 128/split)
#define NTIL 32    // channel tiles in gate kernel (2048/64)

// Scratch (static __device__ globals: allocation-free rule)
__device__ float g_pooled[Bb * Cc];            // max_hw(body*A*face), 0 for non-front rows
__device__ float g_bmean [Bb * Cc];            // mean_hw(body)
__device__ float g_hp    [S1 * Bb * HIDn];     // split-K partials of pooled @ W1^T
__device__ float g_h     [Bb * HIDn];          // relu(sum hp + b1)
__device__ float g_zp    [NTIL * NAT * Bb];    // per-n-tile partials of gap @ Wl^T, [nt][j][b]

// ---------------------------------------------------------------------------
// K1: streaming pass, float4 loads. Each warp: 8 contiguous channels =
// 96 float4 = 3 fully-active coalesced iterations. Reduction via smem
// (4 threads/channel, stride-3 conflict-free) + 2 shfl levels.
// ---------------------------------------------------------------------------
__global__ void __launch_bounds__(256) k1_reduce(
    const float* __restrict__ body, const float* __restrict__ face,
    const float* __restrict__ Af,   const int*   __restrict__ pose)
{
    __shared__ float sm_s[8][96];
    __shared__ float sm_m[8][96];
    __shared__ float out_s[64], out_m[64];
    int tid  = threadIdx.x;
    int wid  = tid >> 5;
    int lane = tid & 31;
    int blk_ch = blockIdx.x * 64;          // block = 64 channels of ONE b
    int b = blk_ch >> 11;
    bool front = (pose[b] == 1);
    int wbase = blk_ch + wid * 8;          // this warp's first channel index

    const float4* bp4 = (const float4*)body + (size_t)wbase * 12;
    float4 bv[3];
    #pragma unroll
    for (int k = 0; k < 3; k++)
        bv[k] = bp4[k * 32 + lane];
    if (front) {
        const float4* fp4 = (const float4*)face + (size_t)wbase * 12;
        const float4* ap4 = (const float4*)Af   + (size_t)(wbase & (Cc - 1)) * 12;
        #pragma unroll
        for (int k = 0; k < 3; k++) {
            float4 fv = fp4[k * 32 + lane];
            float4 av = ap4[k * 32 + lane];
            float m01 = fmaxf(bv[k].x * av.x * fv.x, bv[k].y * av.y * fv.y);
            float m23 = fmaxf(bv[k].z * av.z * fv.z, bv[k].w * av.w * fv.w);
            sm_m[wid][k * 32 + lane] = fmaxf(m01, m23);
        }
    }
    #pragma unroll
    for (int k = 0; k < 3; k++)
        sm_s[wid][k * 32 + lane] = (bv[k].x + bv[k].y) + (bv[k].z + bv[k].w);
    __syncthreads();

    // Phase 2: 4 threads per channel, 3 partials each, then 2 shfl levels.
    {
        int chl = tid >> 2;                // 0..63 local channel
        int w2  = chl >> 3;                // source warp
        int off = (chl & 7) * 12 + (tid & 3) * 3;
        float ss = sm_s[w2][off] + sm_s[w2][off + 1] + sm_s[w2][off + 2];
        ss += __shfl_xor_sync(0xffffffffu, ss, 1);
        ss += __shfl_xor_sync(0xffffffffu, ss, 2);
        float mm = 0.f;
        if (front) {
            mm = fmaxf(fmaxf(sm_m[w2][off], sm_m[w2][off + 1]), sm_m[w2][off + 2]);
            mm = fmaxf(mm, __shfl_xor_sync(0xffffffffu, mm, 1));
            mm = fmaxf(mm, __shfl_xor_sync(0xffffffffu, mm, 2));
        }
        if ((tid & 3) == 0) {
            out_s[chl] = ss * (1.0f / 48.0f);
            out_m[chl] = mm;
        }
    }
    __syncthreads();
    if (tid < 64)        g_bmean [blk_ch + tid]      = out_s[tid];
    else if (tid < 128)  g_pooled[blk_ch + tid - 64] = out_m[tid - 64];
}

// ---------------------------------------------------------------------------
// GEMM1 split-K: hp[s] = pooled[512, k-chunk] @ W1[128, k-chunk]^T
// ---------------------------------------------------------------------------
__global__ void __launch_bounds__(256) gemm1(
    const float* __restrict__ A, const float* __restrict__ Bw,
    float* __restrict__ hp)
{
    __shared__ float As[16][68];
    __shared__ float Bs[16][68];
    int s  = blockIdx.z;
    int m0 = blockIdx.x * 64;
    int n0 = blockIdx.y * 64;
    int k0 = s * (Cc / S1);
    int tid = threadIdx.x;
    int tx = tid & 15, ty = tid >> 4;
    int r  = tid >> 2;
    int q  = (tid & 3) * 4;
    float acc[4][4] = {};

    const float* ap = &A [(size_t)(m0 + r) * Cc + k0 + q];
    const float* bp = &Bw[(size_t)(n0 + r) * Cc + k0 + q];
    float4 areg = *(const float4*)ap;
    float4 breg = *(const float4*)bp;

    #pragma unroll
    for (int kt = 0; kt < Cc / S1; kt += 16) {
        As[q+0][r] = areg.x; As[q+1][r] = areg.y; As[q+2][r] = areg.z; As[q+3][r] = areg.w;
        Bs[q+0][r] = breg.x; Bs[q+1][r] = breg.y; Bs[q+2][r] = breg.z; Bs[q+3][r] = breg.w;
        __syncthreads();
        if (kt + 16 < Cc / S1) {
            areg = *(const float4*)(ap + kt + 16);
            breg = *(const float4*)(bp + kt + 16);
        }
        #pragma unroll
        for (int kk = 0; kk < 16; kk++) {
            float4 a4 = *(const float4*)&As[kk][ty * 4];
            float4 b4 = *(const float4*)&Bs[kk][tx * 4];
            float a[4]  = {a4.x, a4.y, a4.z, a4.w};
            float bb[4] = {b4.x, b4.y, b4.z, b4.w};
            #pragma unroll
            for (int i = 0; i < 4; i++)
                #pragma unroll
                for (int j = 0; j < 4; j++)
                    acc[i][j] = fmaf(a[i], bb[j], acc[i][j]);
        }
        __syncthreads();
    }
    #pragma unroll
    for (int i = 0; i < 4; i++) {
        int m = m0 + ty * 4 + i;
        #pragma unroll
        for (int j = 0; j < 4; j++) {
            int n = n0 + tx * 4 + j;
            hp[((size_t)s * Bb + m) * HIDn + n] = acc[i][j];
        }
    }
}

// ---------------------------------------------------------------------------
// hreduce: h = relu(sum_s hp[s] + b1)
// ---------------------------------------------------------------------------
__global__ void __launch_bounds__(256) hreduce(const float* __restrict__ b1v)
{
    int i4 = blockIdx.x * 256 + threadIdx.x;
    float4 v = *(const float4*)&g_hp[(size_t)i4 * 4];
    #pragma unroll
    for (int s = 1; s < S1; s++) {
        float4 t = *(const float4*)&g_hp[(size_t)s * (Bb * HIDn) + (size_t)i4 * 4];
        v.x += t.x; v.y += t.y; v.z += t.z; v.w += t.w;
    }
    float4 bv = *(const float4*)&b1v[(i4 & 31) * 4];
    v.x = fmaxf(v.x + bv.x, 0.f);
    v.y = fmaxf(v.y + bv.y, 0.f);
    v.z = fmaxf(v.z + bv.z, 0.f);
    v.w = fmaxf(v.w + bv.w, 0.f);
    *(float4*)&g_h[(size_t)i4 * 4] = v;
}

// ---------------------------------------------------------------------------
// GATE: 32(batch)x64(chan) tile, 128 threads, grid 512 (less wave tail).
// gap tile = bmean + front*sigmoid(h @ W2^T + b2), fused z-partial epilogue.
// ---------------------------------------------------------------------------
__global__ void __launch_bounds__(128) gemm_gate(
    const float* __restrict__ W2,  const float* __restrict__ b2v,
    const float* __restrict__ Wl,  const int*   __restrict__ pose)
{
    __shared__ __align__(16) float smemBuf[64 * 36 + 64 * 68];   // 26624 B
    float (*As)[36]   = (float(*)[36]) smemBuf;                  // [16][36]
    float (*Bs)[68]   = (float(*)[68])(smemBuf + 16 * 36);       // [16][68]
    float (*gapT)[36] = (float(*)[36]) smemBuf;                  // [64][36] (chan-major, 32 rows)
    float (*WlT)[68]  = (float(*)[68])(smemBuf + 64 * 36);       // [64][68] (j>=51 zero)

    int m0 = blockIdx.x * 32;
    int n0 = blockIdx.y * 64;
    int tid = threadIdx.x;
    int tx = tid & 15, ty = tid >> 4;       // ty 0..7
    int ra = tid >> 2;                      // A loader row 0..31
    int qa = (tid & 3) * 4;
    int rb = tid >> 1;                      // B loader row 0..63
    int qb = (tid & 1) * 8;
    float acc[4][4] = {};

    const float* ap = &g_h[(size_t)(m0 + ra) * HIDn + qa];
    const float* bp = &W2 [(size_t)(n0 + rb) * HIDn + qb];
    float4 areg  = *(const float4*)ap;
    float4 breg0 = *(const float4*)bp;
    float4 breg1 = *(const float4*)(bp + 4);

    #pragma unroll
    for (int kt = 0; kt < HIDn; kt += 16) {
        As[qa+0][ra] = areg.x; As[qa+1][ra] = areg.y; As[qa+2][ra] = areg.z; As[qa+3][ra] = areg.w;
        Bs[qb+0][rb] = breg0.x; Bs[qb+1][rb] = breg0.y; Bs[qb+2][rb] = breg0.z; Bs[qb+3][rb] = breg0.w;
        Bs[qb+4][rb] = breg1.x; Bs[qb+5][rb] = breg1.y; Bs[qb+6][rb] = breg1.z; Bs[qb+7][rb] = breg1.w;
        __syncthreads();
        if (kt + 16 < HIDn) {
            areg  = *(const float4*)(ap + kt + 16);
            breg0 = *(const float4*)(bp + kt + 16);
            breg1 = *(const float4*)(bp + kt + 20);
        }
        #pragma unroll
        for (int kk = 0; kk < 16; kk++) {
            float4 a4 = *(const float4*)&As[kk][ty * 4];
            float4 b4 = *(const float4*)&Bs[kk][tx * 4];
            float a[4]  = {a4.x, a4.y, a4.z, a4.w};
            float bb[4] = {b4.x, b4.y, b4.z, b4.w};
            #pragma unroll
            for (int i = 0; i < 4; i++)
                #pragma unroll
                for (int j = 0; j < 4; j++)
                    acc[i][j] = fmaf(a[i], bb[j], acc[i][j]);
        }
        __syncthreads();
    }
    // mainloop ends with __syncthreads(): smem free to reuse.

    // gap values -> gapT (chan-major)
    #pragma unroll
    for (int i = 0; i < 4; i++) {
        int m = m0 + ty * 4 + i;
        float fr = (pose[m] == 1) ? 1.0f : 0.0f;
        #pragma unroll
        for (int j = 0; j < 4; j++) {
            int n = n0 + tx * 4 + j;
            float v = acc[i][j] + b2v[n];
            float g = 1.0f / (1.0f + expf(-v));
            gapT[tx * 4 + j][ty * 4 + i] =
                g_bmean[(size_t)m * Cc + n] + fr * g;
        }
    }
    // Wl chunk (51 attrs x 64 channels) transposed+padded
    for (int idx = tid; idx < 64 * 68; idx += 128) {
        int cc = idx / 68, j = idx - cc * 68;
        WlT[cc][j] = (j < NAT) ? Wl[(size_t)j * Cc + n0 + cc] : 0.f;
    }
    __syncthreads();

    // mini-GEMM: zpart[row, attr] = sum_cc gapT[cc][row] * WlT[cc][attr]
    float acc2[4][4] = {};
    #pragma unroll 8
    for (int cc = 0; cc < 64; cc++) {
        float4 g4 = *(const float4*)&gapT[cc][ty * 4];
        float4 w4 = *(const float4*)&WlT [cc][tx * 4];
        float gg[4] = {g4.x, g4.y, g4.z, g4.w};
        float ww[4] = {w4.x, w4.y, w4.z, w4.w};
        #pragma unroll
        for (int i = 0; i < 4; i++)
            #pragma unroll
            for (int j = 0; j < 4; j++)
                acc2[i][j] = fmaf(gg[i], ww[j], acc2[i][j]);
    }
    int nt = blockIdx.y;
    #pragma unroll
    for (int j = 0; j < 4; j++) {
        int attr = tx * 4 + j;
        if (attr < NAT) {
            #pragma unroll
            for (int i = 0; i < 4; i++) {
                int m = m0 + ty * 4 + i;
                g_zp[((size_t)nt * NAT + attr) * Bb + m] = acc2[i][j];
            }
        }
    }
}

// ---------------------------------------------------------------------------
// BN: one block per attribute.
// ---------------------------------------------------------------------------
__global__ void __launch_bounds__(256) bn_kernel(
    const float* __restrict__ blv, const float* __restrict__ gam,
    const float* __restrict__ bet, float* __restrict__ out)
{
    __shared__ float zbuf[Bb];
    __shared__ float red[256];
    int j   = blockIdx.x;
    int tid = threadIdx.x;
    float bias = blv[j];
    float lsum = 0.f;
    for (int b = tid; b < Bb; b += 256) {
        float z = bias;
        #pragma unroll
        for (int nt = 0; nt < NTIL; nt++)
            z += g_zp[((size_t)nt * NAT + j) * Bb + b];
        zbuf[b] = z;
        lsum += z;
    }
    red[tid] = lsum;
    __syncthreads();
    for (int off = 128; off; off >>= 1) {
        if (tid < off) red[tid] += red[tid + off];
        __syncthreads();
    }
    float mu = red[0] * (1.0f / Bb);
    __syncthreads();
    float lvar = 0.f;
    for (int b = tid; b < Bb; b += 256) {
        float d = zbuf[b] - mu;
        lvar += d * d;
    }
    red[tid] = lvar;
    __syncthreads();
    for (int off = 128; off; off >>= 1) {
        if (tid < off) red[tid] += red[tid + off];
        __syncthreads();
    }
    float inv = rsqrtf(red[0] * (1.0f / Bb) + 1e-5f);
    float ga = gam[j], be = bet[j];
    for (int b = tid; b < Bb; b += 256)
        out[(size_t)b * NAT + j] = ga * (zbuf[b] - mu) * inv + be;
}

// ---------------------------------------------------------------------------
extern "C" void kernel_launch(void* const* d_in, const int* in_sizes, int n_in,
                              void* d_out, int out_size)
{
    const float* body = (const float*)d_in[0];
    const float* face = (const float*)d_in[1];
    const int*   pose = (const int*)  d_in[2];
    const float* Af   = (const float*)d_in[3];
    const float* W1   = (const float*)d_in[4];
    const float* b1v  = (const float*)d_in[5];
    const float* W2   = (const float*)d_in[6];
    const float* b2v  = (const float*)d_in[7];
    const float* Wl   = (const float*)d_in[8];
    const float* blv  = (const float*)d_in[9];
    const float* gam  = (const float*)d_in[10];
    const float* bet  = (const float*)d_in[11];
    float* out = (float*)d_out;

    float *pooled_p, *hp_p;
    cudaGetSymbolAddress((void**)&pooled_p, g_pooled);
    cudaGetSymbolAddress((void**)&hp_p,     g_hp);

    // 1) streaming reduce: pooled max + body mean (64 channels/block)
    k1_reduce<<<(Bb * Cc) / 64, 256>>>(body, face, Af, pose);
    // 2) hp[s] = pooled @ W1^T  (16-way split-K partials)
    gemm1<<<dim3(Bb / 64, HIDn / 64, S1), 256>>>(pooled_p, W1, hp_p);
    // 3) h = relu(sum hp + b1)
    hreduce<<<(Bb * HIDn / 4) / 256, 256>>>(b1v);
    // 4) gate GEMM + fused z-partial epilogue (32x64 tiles, grid 512)
    gemm_gate<<<dim3(Bb / 32, NTIL), 128>>>(W2, b2v, Wl, pose);
    // 5) reduce partials + bias + batchnorm
    bn_kernel<<<NAT, 256>>>(blv, gam, bet, out);
}